// round 3
// baseline (speedup 1.0000x reference)
#include <cuda_runtime.h>
#include <math_constants.h>

// Problem constants (fixed by reference: B=16, T=2048, D=256, K=4096)
#define N_TOK 32768
#define DIM   256
#define KCB   4096

// Output layout in d_out (f32):
//   [0]                      c_loss
//   [1 .. 1+N*D)             quantized (starts at +4B: NOT 16B-aligned)
//   [1+N*D .. 1+N*D+N)       encoding_index as float

// Scratch (device globals; no allocations allowed)
__device__ float g_S[N_TOK];
__device__ float g_c[KCB];
__device__ int   g_idx[N_TOK];
__device__ float g_loss[N_TOK];

// ---- packed f32x2 helpers (Blackwell dual-rate FP32) ------------------------
__device__ __forceinline__ void ffma2(unsigned long long& d,
                                      unsigned long long a,
                                      unsigned long long b) {
    asm("fma.rn.f32x2 %0, %1, %2, %0;" : "+l"(d) : "l"(a), "l"(b));
}
__device__ __forceinline__ unsigned long long dup_f32(float v) {
    unsigned long long r;
    asm("mov.b64 %0, {%1, %1};" : "=l"(r) : "r"(__float_as_uint(v)));
    return r;
}
__device__ __forceinline__ void unpack_f32x2(unsigned long long v, float& lo, float& hi) {
    asm("mov.b64 {%0, %1}, %2;" : "=f"(lo), "=f"(hi) : "l"(v));
}

// ---------------------------------------------------------------------------
// Kernel 1: per-row sums of squares, exact fp32 sequential rounding.
// ---------------------------------------------------------------------------
__global__ void prep_kernel(const float* __restrict__ X, const float* __restrict__ E) {
    int i = blockIdx.x * blockDim.x + threadIdx.x;
    if (i < N_TOK) {
        const float4* row = reinterpret_cast<const float4*>(X + (size_t)i * DIM);
        float s = 0.0f;
        #pragma unroll 8
        for (int j = 0; j < DIM / 4; j++) {
            float4 v = row[j];
            s = __fadd_rn(s, __fmul_rn(v.x, v.x));
            s = __fadd_rn(s, __fmul_rn(v.y, v.y));
            s = __fadd_rn(s, __fmul_rn(v.z, v.z));
            s = __fadd_rn(s, __fmul_rn(v.w, v.w));
        }
        g_S[i] = s;
    }
    if (i < KCB) {
        const float4* row = reinterpret_cast<const float4*>(E + (size_t)i * DIM);
        float s = 0.0f;
        #pragma unroll 8
        for (int j = 0; j < DIM / 4; j++) {
            float4 v = row[j];
            s = __fadd_rn(s, __fmul_rn(v.x, v.x));
            s = __fadd_rn(s, __fmul_rn(v.y, v.y));
            s = __fadd_rn(s, __fmul_rn(v.z, v.z));
            s = __fadd_rn(s, __fmul_rn(v.w, v.w));
        }
        g_c[i] = s;
    }
}

// ---------------------------------------------------------------------------
// Kernel 2: fused GEMM (X @ E^T) + argmin, packed f32x2 FFMA2 math.
// BM=64 tokens x BN=128 codes, BK=16, 128 threads.
// Microtile: 8 tokens x 4 code-pairs (= 8 codes). Each FFMA2 half executes the
// identical fp32 FMA chain as the scalar version -> results bit-identical.
// X tile stored DUPLICATED in smem ((x,x) pairs); E tile stored normally so
// consecutive codes form the (e_j, e_{j+1}) packed operand.
// ---------------------------------------------------------------------------
#define BM 64
#define BN 128
#define BK 16
#define NCHUNK (DIM / BK)   // 16
#define NTILE  (KCB / BN)   // 32
#define XSTR 132            // padded row stride (words), 16B-aligned, conflict-free STS

__global__ __launch_bounds__(128) void argmin_kernel(const float* __restrict__ X,
                                                     const float* __restrict__ E,
                                                     float* __restrict__ out_idx_f) {
    __shared__ __align__(16) float Xs[2][BK][XSTR]; // duplicated tokens: token t at 2t,2t+1
    __shared__ __align__(16) float Es[2][BK][BN];

    const int tid = threadIdx.x;
    const int tx = tid & 15;        // code direction, 16 threads (8 codes each)
    const int ty = tid >> 4;        // token direction, 8 threads (8 tokens each)
    const int nb = blockIdx.x * BM;

    float sreg[8];
    #pragma unroll
    for (int i = 0; i < 8; i++) sreg[i] = g_S[nb + ty * 8 + i];

    float best[8];
    int   bidx[8];
    #pragma unroll
    for (int i = 0; i < 8; i++) { best[i] = CUDART_INF_F; bidx[i] = 0x7fffffff; }

    // Per-thread global-load coordinates (same as scalar version)
    const int xq0_tok = tid >> 2, xq0_d = (tid & 3) * 4;
    const int xq1_tok = (tid + 128) >> 2, xq1_d = ((tid + 128) & 3) * 4;

    for (int ct = 0; ct < NTILE; ct++) {
        unsigned long long acc[8][4];
        #pragma unroll
        for (int i = 0; i < 8; i++)
            #pragma unroll
            for (int jp = 0; jp < 4; jp++) acc[i][jp] = 0ull;

        // ---- prologue: load chunk 0 into buffer 0 ----
        float4 xr0, xr1, er[4];
        {
            xr0 = *reinterpret_cast<const float4*>(X + (size_t)(nb + xq0_tok) * DIM + xq0_d);
            xr1 = *reinterpret_cast<const float4*>(X + (size_t)(nb + xq1_tok) * DIM + xq1_d);
            #pragma unroll
            for (int j = 0; j < 4; j++) {
                int q = tid + j * 128;
                er[j] = *reinterpret_cast<const float4*>(E + (size_t)(ct * BN + (q >> 2)) * DIM + (q & 3) * 4);
            }
            // duplicated X stores (STS.64 of (v,v))
            *reinterpret_cast<unsigned long long*>(&Xs[0][xq0_d + 0][2 * xq0_tok]) = dup_f32(xr0.x);
            *reinterpret_cast<unsigned long long*>(&Xs[0][xq0_d + 1][2 * xq0_tok]) = dup_f32(xr0.y);
            *reinterpret_cast<unsigned long long*>(&Xs[0][xq0_d + 2][2 * xq0_tok]) = dup_f32(xr0.z);
            *reinterpret_cast<unsigned long long*>(&Xs[0][xq0_d + 3][2 * xq0_tok]) = dup_f32(xr0.w);
            *reinterpret_cast<unsigned long long*>(&Xs[0][xq1_d + 0][2 * xq1_tok]) = dup_f32(xr1.x);
            *reinterpret_cast<unsigned long long*>(&Xs[0][xq1_d + 1][2 * xq1_tok]) = dup_f32(xr1.y);
            *reinterpret_cast<unsigned long long*>(&Xs[0][xq1_d + 2][2 * xq1_tok]) = dup_f32(xr1.z);
            *reinterpret_cast<unsigned long long*>(&Xs[0][xq1_d + 3][2 * xq1_tok]) = dup_f32(xr1.w);
            #pragma unroll
            for (int j = 0; j < 4; j++) {
                int q = tid + j * 128;
                int c = q >> 2, d = (q & 3) * 4;
                Es[0][d + 0][c] = er[j].x; Es[0][d + 1][c] = er[j].y;
                Es[0][d + 2][c] = er[j].z; Es[0][d + 3][c] = er[j].w;
            }
        }
        __syncthreads();

        int p = 0;
        for (int dc = 0; dc < NCHUNK; dc++) {
            if (dc < NCHUNK - 1) {
                const int dn = dc + 1;
                xr0 = *reinterpret_cast<const float4*>(X + (size_t)(nb + xq0_tok) * DIM + dn * BK + xq0_d);
                xr1 = *reinterpret_cast<const float4*>(X + (size_t)(nb + xq1_tok) * DIM + dn * BK + xq1_d);
                #pragma unroll
                for (int j = 0; j < 4; j++) {
                    int q = tid + j * 128;
                    er[j] = *reinterpret_cast<const float4*>(E + (size_t)(ct * BN + (q >> 2)) * DIM + dn * BK + (q & 3) * 4);
                }
            }
            // compute on buffer p: 6x LDS.128 + 32x FFMA2 per kk
            #pragma unroll
            for (int kk = 0; kk < BK; kk++) {
                const ulonglong2* ap = reinterpret_cast<const ulonglong2*>(&Xs[p][kk][ty * 16]);
                const ulonglong2* bp = reinterpret_cast<const ulonglong2*>(&Es[p][kk][tx * 8]);
                ulonglong2 a01 = ap[0], a23 = ap[1], a45 = ap[2], a67 = ap[3];
                ulonglong2 b01 = bp[0], b23 = bp[1];
                unsigned long long a[8] = {a01.x, a01.y, a23.x, a23.y, a45.x, a45.y, a67.x, a67.y};
                unsigned long long b[4] = {b01.x, b01.y, b23.x, b23.y};
                #pragma unroll
                for (int i = 0; i < 8; i++)
                    #pragma unroll
                    for (int jp = 0; jp < 4; jp++)
                        ffma2(acc[i][jp], a[i], b[jp]);
            }
            if (dc < NCHUNK - 1) {
                int np = p ^ 1;
                *reinterpret_cast<unsigned long long*>(&Xs[np][xq0_d + 0][2 * xq0_tok]) = dup_f32(xr0.x);
                *reinterpret_cast<unsigned long long*>(&Xs[np][xq0_d + 1][2 * xq0_tok]) = dup_f32(xr0.y);
                *reinterpret_cast<unsigned long long*>(&Xs[np][xq0_d + 2][2 * xq0_tok]) = dup_f32(xr0.z);
                *reinterpret_cast<unsigned long long*>(&Xs[np][xq0_d + 3][2 * xq0_tok]) = dup_f32(xr0.w);
                *reinterpret_cast<unsigned long long*>(&Xs[np][xq1_d + 0][2 * xq1_tok]) = dup_f32(xr1.x);
                *reinterpret_cast<unsigned long long*>(&Xs[np][xq1_d + 1][2 * xq1_tok]) = dup_f32(xr1.y);
                *reinterpret_cast<unsigned long long*>(&Xs[np][xq1_d + 2][2 * xq1_tok]) = dup_f32(xr1.z);
                *reinterpret_cast<unsigned long long*>(&Xs[np][xq1_d + 3][2 * xq1_tok]) = dup_f32(xr1.w);
                #pragma unroll
                for (int j = 0; j < 4; j++) {
                    int q = tid + j * 128;
                    int c = q >> 2, d = (q & 3) * 4;
                    Es[np][d + 0][c] = er[j].x; Es[np][d + 1][c] = er[j].y;
                    Es[np][d + 2][c] = er[j].z; Es[np][d + 3][c] = er[j].w;
                }
                __syncthreads();
                p = np;
            }
        }

        // ---- epilogue: identical d2 rounding chain + running argmin ----
        float cj[8];
        #pragma unroll
        for (int j = 0; j < 8; j++) cj[j] = __ldg(&g_c[ct * BN + tx * 8 + j]);
        #pragma unroll
        for (int i = 0; i < 8; i++) {
            #pragma unroll
            for (int jp = 0; jp < 4; jp++) {
                float mlo, mhi;
                unpack_f32x2(acc[i][jp], mlo, mhi);
                int code0 = ct * BN + tx * 8 + 2 * jp;
                float t0  = fmaf(-2.0f, mlo, sreg[i]);
                float d20 = __fadd_rn(t0, cj[2 * jp]);
                if (d20 < best[i]) { best[i] = d20; bidx[i] = code0; }
                float t1  = fmaf(-2.0f, mhi, sreg[i]);
                float d21 = __fadd_rn(t1, cj[2 * jp + 1]);
                if (d21 < best[i]) { best[i] = d21; bidx[i] = code0 + 1; }
            }
        }
        __syncthreads();
    }

    // Cross-thread lexicographic (val, idx) min over tx lanes.
    #pragma unroll
    for (int off = 8; off >= 1; off >>= 1) {
        #pragma unroll
        for (int i = 0; i < 8; i++) {
            float ov = __shfl_xor_sync(0xffffffffu, best[i], off);
            int   oi = __shfl_xor_sync(0xffffffffu, bidx[i], off);
            if (ov < best[i] || (ov == best[i] && oi < bidx[i])) {
                best[i] = ov; bidx[i] = oi;
            }
        }
    }
    if (tx == 0) {
        #pragma unroll
        for (int i = 0; i < 8; i++) {
            int tok = nb + ty * 8 + i;
            g_idx[tok] = bidx[i];
            out_idx_f[tok] = (float)bidx[i];
        }
    }
}

// ---------------------------------------------------------------------------
// Kernel 3: gather + straight-through output + per-token loss.
// Quantized region is only 4B-aligned -> scalar stores.
// ---------------------------------------------------------------------------
__global__ void output_kernel(const float* __restrict__ X, const float* __restrict__ E,
                              float* __restrict__ out_q) {
    int warp = (blockIdx.x * blockDim.x + threadIdx.x) >> 5;
    int lane = threadIdx.x & 31;
    if (warp >= N_TOK) return;
    int code = g_idx[warp];
    const float4* xr = reinterpret_cast<const float4*>(X + (size_t)warp * DIM);
    const float4* er = reinterpret_cast<const float4*>(E + (size_t)code * DIM);
    float* qr = out_q + (size_t)warp * DIM;

    float ls = 0.0f;
    #pragma unroll
    for (int j = lane; j < DIM / 4; j += 32) {
        float4 x = xr[j], e = er[j];
        float4 d, o;
        d.x = __fadd_rn(e.x, -x.x); d.y = __fadd_rn(e.y, -x.y);
        d.z = __fadd_rn(e.z, -x.z); d.w = __fadd_rn(e.w, -x.w);
        ls = __fadd_rn(ls, __fmul_rn(d.x, d.x));
        ls = __fadd_rn(ls, __fmul_rn(d.y, d.y));
        ls = __fadd_rn(ls, __fmul_rn(d.z, d.z));
        ls = __fadd_rn(ls, __fmul_rn(d.w, d.w));
        o.x = __fadd_rn(x.x, d.x); o.y = __fadd_rn(x.y, d.y);
        o.z = __fadd_rn(x.z, d.z); o.w = __fadd_rn(x.w, d.w);
        qr[j * 4 + 0] = o.x;
        qr[j * 4 + 1] = o.y;
        qr[j * 4 + 2] = o.z;
        qr[j * 4 + 3] = o.w;
    }
    #pragma unroll
    for (int off = 16; off >= 1; off >>= 1)
        ls = __fadd_rn(ls, __shfl_xor_sync(0xffffffffu, ls, off));
    if (lane == 0) g_loss[warp] = ls;
}

// ---------------------------------------------------------------------------
// Kernel 4: deterministic double-precision loss reduce -> c_loss.
// ---------------------------------------------------------------------------
__global__ void finalize_kernel(float* __restrict__ out) {
    __shared__ double sh[256];
    double s = 0.0;
    for (int i = threadIdx.x; i < N_TOK; i += 256) s += (double)g_loss[i];
    sh[threadIdx.x] = s;
    __syncthreads();
    for (int off = 128; off >= 1; off >>= 1) {
        if (threadIdx.x < off) sh[threadIdx.x] += sh[threadIdx.x + off];
        __syncthreads();
    }
    if (threadIdx.x == 0)
        out[0] = (float)(0.5 * sh[0] / ((double)N_TOK * (double)DIM));
}

// ---------------------------------------------------------------------------
extern "C" void kernel_launch(void* const* d_in, const int* in_sizes, int n_in,
                              void* d_out, int out_size) {
    const float* X = (const float*)d_in[0];   // embedding_tokens [N, D]
    const float* E = (const float*)d_in[1];   // embeddings       [K, D]
    float* out = (float*)d_out;
    float* out_q   = out + 1;
    float* out_idx = out + 1 + (size_t)N_TOK * DIM;

    prep_kernel<<<(N_TOK + 255) / 256, 256>>>(X, E);
    argmin_kernel<<<N_TOK / BM, 128>>>(X, E, out_idx);
    output_kernel<<<(N_TOK * 32 + 255) / 256, 256>>>(X, E, out_q);
    finalize_kernel<<<1, 256>>>(out);
}